// round 7
// baseline (speedup 1.0000x reference)
#include <cuda_runtime.h>
#include <cuda_bf16.h>
#include <cstdint>

#define N_NODES 100000
#define E_MAX   1200000
#define D 64

#define SCAN_CHUNK 1024
#define N_CHUNKS   ((N_NODES + SCAN_CHUNK - 1) / SCAN_CHUNK)   // 98
#define N_PADDED   (N_CHUNKS * SCAN_CHUNK)                     // 100352

// Device scratch (no allocations allowed).
__device__ float g_h[N_NODES * D];              // x @ W (unscaled), 25.6 MB
__device__ int   g_deg_out[N_NODES];
__device__ int   g_deg_in[N_NODES];
__device__ float g_norm_src[N_NODES];
__device__ int   g_rowptr[N_PADDED + 1];
__device__ int   g_cursor[N_NODES];
__device__ int   g_scan_val[N_CHUNKS];          // -1 = not published, else chunk sum
__device__ int2  g_cedge[E_MAX];                // {src, bits(norm_src[src])} per CSR slot

// ---------------------------------------------------------------------------
__global__ void init_kernel() {
    int i = blockIdx.x * blockDim.x + threadIdx.x;
    if (i < N_NODES) { g_deg_out[i] = 0; g_deg_in[i] = 0; }
    if (i < N_CHUNKS) g_scan_val[i] = -1;
}

// ---------------------------------------------------------------------------
// Degree histogram, 4 edges per thread via int4 loads.
__global__ void degree_kernel(const int* __restrict__ src,
                              const int* __restrict__ dst, int E) {
    int i4 = blockIdx.x * blockDim.x + threadIdx.x;
    int base = i4 * 4;
    if (base + 3 < E) {
        int4 s = *(const int4*)(src + base);
        int4 d = *(const int4*)(dst + base);
        atomicAdd(&g_deg_out[s.x], 1); atomicAdd(&g_deg_out[s.y], 1);
        atomicAdd(&g_deg_out[s.z], 1); atomicAdd(&g_deg_out[s.w], 1);
        atomicAdd(&g_deg_in [d.x], 1); atomicAdd(&g_deg_in [d.y], 1);
        atomicAdd(&g_deg_in [d.z], 1); atomicAdd(&g_deg_in [d.w], 1);
    } else {
        for (int i = base; i < E; i++) {
            atomicAdd(&g_deg_out[src[i]], 1);
            atomicAdd(&g_deg_in [dst[i]], 1);
        }
    }
}

// ---------------------------------------------------------------------------
// Single-pass exclusive scan of deg_in (decoupled lookback, 98 blocks) and
// norm_src = rsqrt(max(deg_out,1)) as a side product.
__global__ void __launch_bounds__(256) scan_kernel() {
    __shared__ int sh[256];
    const int t    = threadIdx.x;
    const int bid  = blockIdx.x;
    const int base = bid * SCAN_CHUNK + t * 4;

    int v0 = (base + 0 < N_NODES) ? g_deg_in[base + 0] : 0;
    int v1 = (base + 1 < N_NODES) ? g_deg_in[base + 1] : 0;
    int v2 = (base + 2 < N_NODES) ? g_deg_in[base + 2] : 0;
    int v3 = (base + 3 < N_NODES) ? g_deg_in[base + 3] : 0;
    int s  = v0 + v1 + v2 + v3;

    #pragma unroll
    for (int q = 0; q < 4; q++) {
        int i = base + q;
        if (i < N_NODES)
            g_norm_src[i] = rsqrtf(fmaxf((float)g_deg_out[i], 1.f));
    }

    sh[t] = s; __syncthreads();
    #pragma unroll
    for (int off = 1; off < 256; off <<= 1) {
        int x = (t >= off) ? sh[t - off] : 0;
        __syncthreads();
        sh[t] += x;
        __syncthreads();
    }
    const int excl = sh[t] - s;
    if (t == 255) atomicExch(&g_scan_val[bid], sh[255]);

    int part = 0;
    if (t < bid) {
        int v;
        do { v = atomicAdd(&g_scan_val[t], 0); } while (v < 0);
        part = v;
    }
    __syncthreads();
    sh[t] = part; __syncthreads();
    #pragma unroll
    for (int off = 128; off > 0; off >>= 1) {
        if (t < off) sh[t] += sh[t + off];
        __syncthreads();
    }
    const int off0 = sh[0];

    int r0 = off0 + excl;
    g_rowptr[base + 0] = r0;
    g_rowptr[base + 1] = r0 + v0;
    g_rowptr[base + 2] = r0 + v0 + v1;
    g_rowptr[base + 3] = r0 + v0 + v1 + v2;
    if (base + 0 < N_NODES) g_cursor[base + 0] = r0;
    if (base + 1 < N_NODES) g_cursor[base + 1] = r0 + v0;
    if (base + 2 < N_NODES) g_cursor[base + 2] = r0 + v0 + v1;
    if (base + 3 < N_NODES) g_cursor[base + 3] = r0 + v0 + v1 + v2;
}

// ---------------------------------------------------------------------------
// Build CSR-by-dst with norm attached: 2 independent edges per thread (ILP).
__global__ void permute_kernel(const int* __restrict__ src,
                               const int* __restrict__ dst, int E) {
    int i2 = blockIdx.x * blockDim.x + threadIdx.x;
    int i0 = i2 * 2, i1 = i0 + 1;
    if (i1 < E) {
        int s0 = src[i0], s1 = src[i1];
        int d0 = dst[i0], d1 = dst[i1];
        float n0 = g_norm_src[s0], n1 = g_norm_src[s1];
        int slot0 = atomicAdd(&g_cursor[d0], 1);
        int slot1 = atomicAdd(&g_cursor[d1], 1);
        g_cedge[slot0] = make_int2(s0, __float_as_int(n0));
        g_cedge[slot1] = make_int2(s1, __float_as_int(n1));
    } else if (i0 < E) {
        int s0 = src[i0], d0 = dst[i0];
        float n0 = g_norm_src[s0];
        int slot0 = atomicAdd(&g_cursor[d0], 1);
        g_cedge[slot0] = make_int2(s0, __float_as_int(n0));
    }
}

// ---------------------------------------------------------------------------
// Packed f32x2 helpers.
__device__ __forceinline__ void fma2(unsigned long long& d,
                                     unsigned long long a,
                                     unsigned long long b) {
    asm("fma.rn.f32x2 %0, %1, %2, %0;" : "+l"(d) : "l"(a), "l"(b));
}
__device__ __forceinline__ unsigned long long pack2(float x) {
    unsigned long long r;
    asm("mov.b64 %0, {%1,%1};" : "=l"(r) : "f"(x));
    return r;
}

// ---------------------------------------------------------------------------
// h = x @ W (no scaling -> no dependency on degree).
#define XPAD 68
__global__ void __launch_bounds__(128) gemm_kernel(const float* __restrict__ x,
                                                   const float* __restrict__ W) {
    __shared__ float Ws[64 * 64];        // [k][c]
    __shared__ float Xs[128 * XPAD];     // [r][k]

    const int t    = threadIdx.x;
    const int row0 = blockIdx.x * 128;
    const int rows = min(128, N_NODES - row0);

    {
        const float4* W4  = (const float4*)W;
        float4*       Ws4 = (float4*)Ws;
        #pragma unroll
        for (int i = 0; i < 8; i++) Ws4[t + i * 128] = W4[t + i * 128];
    }
    {
        const float4* xg = (const float4*)(x + (size_t)row0 * 64);
        #pragma unroll
        for (int i = 0; i < 16; i++) {
            int idx4 = t + i * 128;
            int r  = idx4 >> 4;
            int c4 = (idx4 & 15) * 4;
            if (r < rows)
                *(float4*)&Xs[r * XPAD + c4] = xg[idx4];
        }
    }
    __syncthreads();

    const int rg = t >> 2;
    const int cq = (t & 3) * 16;
    const int r0 = rg * 4;
    if (r0 >= rows) return;

    unsigned long long acc[4][8];
    #pragma unroll
    for (int r = 0; r < 4; r++)
        #pragma unroll
        for (int c = 0; c < 8; c++) acc[r][c] = 0ull;

    #pragma unroll 2
    for (int kq = 0; kq < 64; kq += 4) {
        float4 xr0 = *(const float4*)&Xs[(r0 + 0) * XPAD + kq];
        float4 xr1 = *(const float4*)&Xs[(r0 + 1) * XPAD + kq];
        float4 xr2 = *(const float4*)&Xs[(r0 + 2) * XPAD + kq];
        float4 xr3 = *(const float4*)&Xs[(r0 + 3) * XPAD + kq];
        const float* xr0f = (const float*)&xr0;
        const float* xr1f = (const float*)&xr1;
        const float* xr2f = (const float*)&xr2;
        const float* xr3f = (const float*)&xr3;

        #pragma unroll
        for (int kk = 0; kk < 4; kk++) {
            unsigned long long xv0 = pack2(xr0f[kk]);
            unsigned long long xv1 = pack2(xr1f[kk]);
            unsigned long long xv2 = pack2(xr2f[kk]);
            unsigned long long xv3 = pack2(xr3f[kk]);
            const ulonglong2* wp = (const ulonglong2*)&Ws[(kq + kk) * 64 + cq];
            ulonglong2 wa = wp[0];
            ulonglong2 wb = wp[1];
            ulonglong2 wc = wp[2];
            ulonglong2 wd = wp[3];
            fma2(acc[0][0], xv0, wa.x); fma2(acc[0][1], xv0, wa.y);
            fma2(acc[0][2], xv0, wb.x); fma2(acc[0][3], xv0, wb.y);
            fma2(acc[0][4], xv0, wc.x); fma2(acc[0][5], xv0, wc.y);
            fma2(acc[0][6], xv0, wd.x); fma2(acc[0][7], xv0, wd.y);
            fma2(acc[1][0], xv1, wa.x); fma2(acc[1][1], xv1, wa.y);
            fma2(acc[1][2], xv1, wb.x); fma2(acc[1][3], xv1, wb.y);
            fma2(acc[1][4], xv1, wc.x); fma2(acc[1][5], xv1, wc.y);
            fma2(acc[1][6], xv1, wd.x); fma2(acc[1][7], xv1, wd.y);
            fma2(acc[2][0], xv2, wa.x); fma2(acc[2][1], xv2, wa.y);
            fma2(acc[2][2], xv2, wb.x); fma2(acc[2][3], xv2, wb.y);
            fma2(acc[2][4], xv2, wc.x); fma2(acc[2][5], xv2, wc.y);
            fma2(acc[2][6], xv2, wd.x); fma2(acc[2][7], xv2, wd.y);
            fma2(acc[3][0], xv3, wa.x); fma2(acc[3][1], xv3, wa.y);
            fma2(acc[3][2], xv3, wb.x); fma2(acc[3][3], xv3, wb.y);
            fma2(acc[3][4], xv3, wc.x); fma2(acc[3][5], xv3, wc.y);
            fma2(acc[3][6], xv3, wd.x); fma2(acc[3][7], xv3, wd.y);
        }
    }

    #pragma unroll
    for (int r = 0; r < 4; r++) {
        int row = row0 + r0 + r;
        if (r0 + r >= rows) break;
        float* outp = g_h + (size_t)row * 64 + cq;
        #pragma unroll
        for (int c = 0; c < 4; c++) {
            float l0, h0, l1, h1;
            asm("mov.b64 {%0,%1}, %2;" : "=f"(l0), "=f"(h0) : "l"(acc[r][2*c+0]));
            asm("mov.b64 {%0,%1}, %2;" : "=f"(l1), "=f"(h1) : "l"(acc[r][2*c+1]));
            float4 v; v.x = l0; v.y = h0; v.z = l1; v.w = h1;
            *(float4*)(outp + 4 * c) = v;
        }
    }
}

// ---------------------------------------------------------------------------
// Pull aggregation: one warp per dst node, lane owns 2 cols.
// Per edge: h[u] * norm_src[u] (norm shipped inside the edge record).
__global__ void __launch_bounds__(256) aggregate_kernel(const float* __restrict__ b,
                                                        float* __restrict__ out) {
    int wg   = (blockIdx.x * blockDim.x + threadIdx.x) >> 5;
    int lane = threadIdx.x & 31;
    if (wg >= N_NODES) return;

    const int beg = g_rowptr[wg];
    const int end = g_rowptr[wg + 1];

    float2 acc0 = make_float2(0.f, 0.f);
    float2 acc1 = make_float2(0.f, 0.f);

    const unsigned long long* cedge = (const unsigned long long*)g_cedge;

    for (int j = beg; j < end; j += 32) {
        int n = min(32, end - j);
        unsigned long long ev = (lane < n) ? __ldg(&cedge[j + lane]) : 0ull;
        int i = 0;
        for (; i + 4 <= n; i += 4) {
            unsigned long long e0 = __shfl_sync(0xffffffff, ev, i);
            unsigned long long e1 = __shfl_sync(0xffffffff, ev, i + 1);
            unsigned long long e2 = __shfl_sync(0xffffffff, ev, i + 2);
            unsigned long long e3 = __shfl_sync(0xffffffff, ev, i + 3);
            int u0 = (int)(unsigned)e0; float n0 = __uint_as_float((unsigned)(e0 >> 32));
            int u1 = (int)(unsigned)e1; float n1 = __uint_as_float((unsigned)(e1 >> 32));
            int u2 = (int)(unsigned)e2; float n2 = __uint_as_float((unsigned)(e2 >> 32));
            int u3 = (int)(unsigned)e3; float n3 = __uint_as_float((unsigned)(e3 >> 32));
            float2 h0 = __ldg((const float2*)(g_h + (size_t)u0 * 64) + lane);
            float2 h1 = __ldg((const float2*)(g_h + (size_t)u1 * 64) + lane);
            float2 h2 = __ldg((const float2*)(g_h + (size_t)u2 * 64) + lane);
            float2 h3 = __ldg((const float2*)(g_h + (size_t)u3 * 64) + lane);
            acc0.x = fmaf(h0.x, n0, acc0.x); acc0.y = fmaf(h0.y, n0, acc0.y);
            acc1.x = fmaf(h1.x, n1, acc1.x); acc1.y = fmaf(h1.y, n1, acc1.y);
            acc0.x = fmaf(h2.x, n2, acc0.x); acc0.y = fmaf(h2.y, n2, acc0.y);
            acc1.x = fmaf(h3.x, n3, acc1.x); acc1.y = fmaf(h3.y, n3, acc1.y);
        }
        for (; i < n; i++) {
            unsigned long long e = __shfl_sync(0xffffffff, ev, i);
            int u = (int)(unsigned)e; float nv = __uint_as_float((unsigned)(e >> 32));
            float2 h = __ldg((const float2*)(g_h + (size_t)u * 64) + lane);
            acc0.x = fmaf(h.x, nv, acc0.x); acc0.y = fmaf(h.y, nv, acc0.y);
        }
    }

    float  norm = rsqrtf(fmaxf((float)(end - beg), 1.f));
    float2 bb   = *(const float2*)(b + lane * 2);
    float2 r;
    r.x = fmaxf((acc0.x + acc1.x) * norm + bb.x, 0.f);
    r.y = fmaxf((acc0.y + acc1.y) * norm + bb.y, 0.f);
    *(float2*)(out + (size_t)wg * 64 + lane * 2) = r;
}

// ---------------------------------------------------------------------------
extern "C" void kernel_launch(void* const* d_in, const int* in_sizes, int n_in,
                              void* d_out, int out_size) {
    const float* x   = (const float*)d_in[0];
    const float* W   = (const float*)d_in[1];
    const float* b   = (const float*)d_in[2];
    const int*   src = (const int*)  d_in[3];
    const int*   dst = (const int*)  d_in[4];
    const int    E   = in_sizes[3];

    float* out = (float*)d_out;

    static cudaStream_t s2 = nullptr;
    static cudaEvent_t  evRoot = nullptr, evB = nullptr;
    if (s2 == nullptr) {
        cudaStreamCreateWithFlags(&s2, cudaStreamNonBlocking);
        cudaEventCreateWithFlags(&evRoot, cudaEventDisableTiming);
        cudaEventCreateWithFlags(&evB, cudaEventDisableTiming);
    }

    // Fork: side stream must join the capture DAG via an event recorded on the
    // capture (legacy) stream BEFORE any side-stream launch.
    cudaEventRecord(evRoot, 0);
    cudaStreamWaitEvent(s2, evRoot, 0);

    // Side chain (graph prep) overlapped with the dense GEMM on stream 0.
    init_kernel<<<(N_NODES + 255) / 256, 256, 0, s2>>>();
    degree_kernel<<<(E / 4 + 255) / 256, 256, 0, s2>>>(src, dst, E);
    scan_kernel<<<N_CHUNKS, 256, 0, s2>>>();
    permute_kernel<<<(E / 2 + 255) / 256, 256, 0, s2>>>(src, dst, E);
    cudaEventRecord(evB, s2);

    gemm_kernel<<<(N_NODES + 127) / 128, 128>>>(x, W);

    cudaStreamWaitEvent(0, evB, 0);
    aggregate_kernel<<<(N_NODES * 32 + 255) / 256, 256>>>(b, out);
}

// round 8
// speedup vs baseline: 1.0348x; 1.0348x over previous
#include <cuda_runtime.h>
#include <cuda_bf16.h>
#include <cstdint>

#define N_NODES 100000
#define E_MAX   1200000
#define D 64

#define SCAN_CHUNK 1024
#define N_CHUNKS   ((N_NODES + SCAN_CHUNK - 1) / SCAN_CHUNK)   // 98
#define N_PADDED   (N_CHUNKS * SCAN_CHUNK)                     // 100352

// Device scratch (no allocations allowed).
__device__ float g_h[N_NODES * D];              // (x@W) * norm_src, 25.6 MB
__device__ int   g_deg_out[N_NODES];
__device__ int   g_deg_in[N_NODES];
__device__ int   g_rowptr[N_PADDED + 1];
__device__ int   g_cursor[N_NODES];
__device__ int   g_scan_val[N_CHUNKS];          // -1 = not published, else chunk sum
__device__ int   g_csrc[E_MAX];                 // src node per CSR slot (grouped by dst)

// ---------------------------------------------------------------------------
// Degree histogram, 4 edges per thread via int4 loads.
__global__ void degree_kernel(const int* __restrict__ src,
                              const int* __restrict__ dst, int E) {
    int i4 = blockIdx.x * blockDim.x + threadIdx.x;
    int base = i4 * 4;
    if (base + 3 < E) {
        int4 s = *(const int4*)(src + base);
        int4 d = *(const int4*)(dst + base);
        atomicAdd(&g_deg_out[s.x], 1); atomicAdd(&g_deg_out[s.y], 1);
        atomicAdd(&g_deg_out[s.z], 1); atomicAdd(&g_deg_out[s.w], 1);
        atomicAdd(&g_deg_in [d.x], 1); atomicAdd(&g_deg_in [d.y], 1);
        atomicAdd(&g_deg_in [d.z], 1); atomicAdd(&g_deg_in [d.w], 1);
    } else {
        for (int i = base; i < E; i++) {
            atomicAdd(&g_deg_out[src[i]], 1);
            atomicAdd(&g_deg_in [dst[i]], 1);
        }
    }
}

// ---------------------------------------------------------------------------
// Single-pass exclusive scan of deg_in with decoupled lookback (98 blocks, one wave).
__global__ void __launch_bounds__(256) scan_kernel() {
    __shared__ int sh[256];
    const int t    = threadIdx.x;
    const int bid  = blockIdx.x;
    const int base = bid * SCAN_CHUNK + t * 4;

    int v0 = (base + 0 < N_NODES) ? g_deg_in[base + 0] : 0;
    int v1 = (base + 1 < N_NODES) ? g_deg_in[base + 1] : 0;
    int v2 = (base + 2 < N_NODES) ? g_deg_in[base + 2] : 0;
    int v3 = (base + 3 < N_NODES) ? g_deg_in[base + 3] : 0;
    int s  = v0 + v1 + v2 + v3;

    sh[t] = s; __syncthreads();
    #pragma unroll
    for (int off = 1; off < 256; off <<= 1) {
        int x = (t >= off) ? sh[t - off] : 0;
        __syncthreads();
        sh[t] += x;
        __syncthreads();
    }
    const int excl = sh[t] - s;
    if (t == 255) atomicExch(&g_scan_val[bid], sh[255]);

    int part = 0;
    if (t < bid) {
        int v;
        do { v = atomicAdd(&g_scan_val[t], 0); } while (v < 0);
        part = v;
    }
    __syncthreads();
    sh[t] = part; __syncthreads();
    #pragma unroll
    for (int off = 128; off > 0; off >>= 1) {
        if (t < off) sh[t] += sh[t + off];
        __syncthreads();
    }
    const int off0 = sh[0];

    int r0 = off0 + excl;
    g_rowptr[base + 0] = r0;
    g_rowptr[base + 1] = r0 + v0;
    g_rowptr[base + 2] = r0 + v0 + v1;
    g_rowptr[base + 3] = r0 + v0 + v1 + v2;
    if (base + 0 < N_NODES) g_cursor[base + 0] = r0;
    if (base + 1 < N_NODES) g_cursor[base + 1] = r0 + v0;
    if (base + 2 < N_NODES) g_cursor[base + 2] = r0 + v0 + v1;
    if (base + 3 < N_NODES) g_cursor[base + 3] = r0 + v0 + v1 + v2;
}

// ---------------------------------------------------------------------------
// Build CSR-by-dst: 4 independent edges per thread (latency hiding; issue was 3.6%).
__global__ void permute_kernel(const int* __restrict__ src,
                               const int* __restrict__ dst, int E) {
    int i4 = blockIdx.x * blockDim.x + threadIdx.x;
    int base = i4 * 4;
    if (base + 3 < E) {
        int4 s = *(const int4*)(src + base);
        int4 d = *(const int4*)(dst + base);
        int p0 = atomicAdd(&g_cursor[d.x], 1);
        int p1 = atomicAdd(&g_cursor[d.y], 1);
        int p2 = atomicAdd(&g_cursor[d.z], 1);
        int p3 = atomicAdd(&g_cursor[d.w], 1);
        g_csrc[p0] = s.x; g_csrc[p1] = s.y;
        g_csrc[p2] = s.z; g_csrc[p3] = s.w;
    } else {
        for (int i = base; i < E; i++) {
            int slot = atomicAdd(&g_cursor[dst[i]], 1);
            g_csrc[slot] = src[i];
        }
    }
}

// ---------------------------------------------------------------------------
// Packed f32x2 helpers.
__device__ __forceinline__ void fma2(unsigned long long& d,
                                     unsigned long long a,
                                     unsigned long long b) {
    asm("fma.rn.f32x2 %0, %1, %2, %0;" : "+l"(d) : "l"(a), "l"(b));
}
__device__ __forceinline__ unsigned long long pack2(float x) {
    unsigned long long r;
    asm("mov.b64 %0, {%1,%1};" : "=l"(r) : "f"(x));
    return r;
}

// ---------------------------------------------------------------------------
// h_scaled = (x @ W) * norm_src. 128 threads, 128x64 tile, 4x16 per thread.
#define XPAD 68
__global__ void __launch_bounds__(128) gemm_scale_kernel(const float* __restrict__ x,
                                                         const float* __restrict__ W) {
    __shared__ float Ws[64 * 64];        // [k][c]
    __shared__ float Xs[128 * XPAD];     // [r][k]

    const int t    = threadIdx.x;
    const int row0 = blockIdx.x * 128;
    const int rows = min(128, N_NODES - row0);

    {
        const float4* W4  = (const float4*)W;
        float4*       Ws4 = (float4*)Ws;
        #pragma unroll
        for (int i = 0; i < 8; i++) Ws4[t + i * 128] = W4[t + i * 128];
    }
    {
        const float4* xg = (const float4*)(x + (size_t)row0 * 64);
        #pragma unroll
        for (int i = 0; i < 16; i++) {
            int idx4 = t + i * 128;
            int r  = idx4 >> 4;
            int c4 = (idx4 & 15) * 4;
            if (r < rows)
                *(float4*)&Xs[r * XPAD + c4] = xg[idx4];
        }
    }
    __syncthreads();

    const int rg = t >> 2;
    const int cq = (t & 3) * 16;
    const int r0 = rg * 4;
    if (r0 >= rows) return;

    unsigned long long acc[4][8];
    #pragma unroll
    for (int r = 0; r < 4; r++)
        #pragma unroll
        for (int c = 0; c < 8; c++) acc[r][c] = 0ull;

    #pragma unroll 2
    for (int kq = 0; kq < 64; kq += 4) {
        float4 xr0 = *(const float4*)&Xs[(r0 + 0) * XPAD + kq];
        float4 xr1 = *(const float4*)&Xs[(r0 + 1) * XPAD + kq];
        float4 xr2 = *(const float4*)&Xs[(r0 + 2) * XPAD + kq];
        float4 xr3 = *(const float4*)&Xs[(r0 + 3) * XPAD + kq];
        const float* xr0f = (const float*)&xr0;
        const float* xr1f = (const float*)&xr1;
        const float* xr2f = (const float*)&xr2;
        const float* xr3f = (const float*)&xr3;

        #pragma unroll
        for (int kk = 0; kk < 4; kk++) {
            unsigned long long xv0 = pack2(xr0f[kk]);
            unsigned long long xv1 = pack2(xr1f[kk]);
            unsigned long long xv2 = pack2(xr2f[kk]);
            unsigned long long xv3 = pack2(xr3f[kk]);
            const ulonglong2* wp = (const ulonglong2*)&Ws[(kq + kk) * 64 + cq];
            ulonglong2 wa = wp[0];
            ulonglong2 wb = wp[1];
            ulonglong2 wc = wp[2];
            ulonglong2 wd = wp[3];
            fma2(acc[0][0], xv0, wa.x); fma2(acc[0][1], xv0, wa.y);
            fma2(acc[0][2], xv0, wb.x); fma2(acc[0][3], xv0, wb.y);
            fma2(acc[0][4], xv0, wc.x); fma2(acc[0][5], xv0, wc.y);
            fma2(acc[0][6], xv0, wd.x); fma2(acc[0][7], xv0, wd.y);
            fma2(acc[1][0], xv1, wa.x); fma2(acc[1][1], xv1, wa.y);
            fma2(acc[1][2], xv1, wb.x); fma2(acc[1][3], xv1, wb.y);
            fma2(acc[1][4], xv1, wc.x); fma2(acc[1][5], xv1, wc.y);
            fma2(acc[1][6], xv1, wd.x); fma2(acc[1][7], xv1, wd.y);
            fma2(acc[2][0], xv2, wa.x); fma2(acc[2][1], xv2, wa.y);
            fma2(acc[2][2], xv2, wb.x); fma2(acc[2][3], xv2, wb.y);
            fma2(acc[2][4], xv2, wc.x); fma2(acc[2][5], xv2, wc.y);
            fma2(acc[2][6], xv2, wd.x); fma2(acc[2][7], xv2, wd.y);
            fma2(acc[3][0], xv3, wa.x); fma2(acc[3][1], xv3, wa.y);
            fma2(acc[3][2], xv3, wb.x); fma2(acc[3][3], xv3, wb.y);
            fma2(acc[3][4], xv3, wc.x); fma2(acc[3][5], xv3, wc.y);
            fma2(acc[3][6], xv3, wd.x); fma2(acc[3][7], xv3, wd.y);
        }
    }

    #pragma unroll
    for (int r = 0; r < 4; r++) {
        int row = row0 + r0 + r;
        if (r0 + r >= rows) break;
        float norm = rsqrtf(fmaxf((float)g_deg_out[row], 1.f));
        float* outp = g_h + (size_t)row * 64 + cq;
        #pragma unroll
        for (int c = 0; c < 4; c++) {
            float l0, h0, l1, h1;
            asm("mov.b64 {%0,%1}, %2;" : "=f"(l0), "=f"(h0) : "l"(acc[r][2*c+0]));
            asm("mov.b64 {%0,%1}, %2;" : "=f"(l1), "=f"(h1) : "l"(acc[r][2*c+1]));
            float4 v;
            v.x = l0 * norm; v.y = h0 * norm; v.z = l1 * norm; v.w = h1 * norm;
            *(float4*)(outp + 4 * c) = v;
        }
    }
}

// ---------------------------------------------------------------------------
// Pull aggregation: one warp per dst node, lane owns 2 cols. 4-deep MLP.
__global__ void __launch_bounds__(256) aggregate_kernel(const float* __restrict__ b,
                                                        float* __restrict__ out) {
    int wg   = (blockIdx.x * blockDim.x + threadIdx.x) >> 5;
    int lane = threadIdx.x & 31;
    if (wg >= N_NODES) return;

    const int beg = g_rowptr[wg];
    const int end = g_rowptr[wg + 1];

    float2 acc0 = make_float2(0.f, 0.f);
    float2 acc1 = make_float2(0.f, 0.f);

    for (int j = beg; j < end; j += 32) {
        int n  = min(32, end - j);
        int sv = (lane < n) ? g_csrc[j + lane] : 0;
        int i  = 0;
        for (; i + 4 <= n; i += 4) {
            int u0 = __shfl_sync(0xffffffff, sv, i);
            int u1 = __shfl_sync(0xffffffff, sv, i + 1);
            int u2 = __shfl_sync(0xffffffff, sv, i + 2);
            int u3 = __shfl_sync(0xffffffff, sv, i + 3);
            float2 h0 = __ldg((const float2*)(g_h + (size_t)u0 * 64) + lane);
            float2 h1 = __ldg((const float2*)(g_h + (size_t)u1 * 64) + lane);
            float2 h2 = __ldg((const float2*)(g_h + (size_t)u2 * 64) + lane);
            float2 h3 = __ldg((const float2*)(g_h + (size_t)u3 * 64) + lane);
            acc0.x += h0.x; acc0.y += h0.y;
            acc1.x += h1.x; acc1.y += h1.y;
            acc0.x += h2.x; acc0.y += h2.y;
            acc1.x += h3.x; acc1.y += h3.y;
        }
        for (; i < n; i++) {
            int u = __shfl_sync(0xffffffff, sv, i);
            float2 h = __ldg((const float2*)(g_h + (size_t)u * 64) + lane);
            acc0.x += h.x; acc0.y += h.y;
        }
    }

    float  norm = rsqrtf(fmaxf((float)(end - beg), 1.f));
    float2 bb   = *(const float2*)(b + lane * 2);
    float2 r;
    r.x = fmaxf((acc0.x + acc1.x) * norm + bb.x, 0.f);
    r.y = fmaxf((acc0.y + acc1.y) * norm + bb.y, 0.f);
    *(float2*)(out + (size_t)wg * 64 + lane * 2) = r;
}

// ---------------------------------------------------------------------------
extern "C" void kernel_launch(void* const* d_in, const int* in_sizes, int n_in,
                              void* d_out, int out_size) {
    const float* x   = (const float*)d_in[0];
    const float* W   = (const float*)d_in[1];
    const float* b   = (const float*)d_in[2];
    const int*   src = (const int*)  d_in[3];
    const int*   dst = (const int*)  d_in[4];
    const int    E   = in_sizes[3];

    float* out = (float*)d_out;

    // One-time setup (first call is the uncaptured correctness run).
    static cudaStream_t s2 = nullptr;
    static cudaEvent_t  evA = nullptr, evB = nullptr;
    static void *p_deg_out = nullptr, *p_deg_in = nullptr, *p_scan_val = nullptr;
    if (s2 == nullptr) {
        cudaStreamCreateWithFlags(&s2, cudaStreamNonBlocking);
        cudaEventCreateWithFlags(&evA, cudaEventDisableTiming);
        cudaEventCreateWithFlags(&evB, cudaEventDisableTiming);
        cudaGetSymbolAddress(&p_deg_out,  g_deg_out);
        cudaGetSymbolAddress(&p_deg_in,   g_deg_in);
        cudaGetSymbolAddress(&p_scan_val, g_scan_val);
    }

    // Zero/seed counters via memset nodes (cheaper than a 391-block kernel).
    cudaMemsetAsync(p_deg_out,  0x00, N_NODES * sizeof(int), 0);
    cudaMemsetAsync(p_deg_in,   0x00, N_NODES * sizeof(int), 0);
    cudaMemsetAsync(p_scan_val, 0xFF, N_CHUNKS * sizeof(int), 0);   // -1

    degree_kernel<<<(E / 4 + 255) / 256, 256>>>(src, dst, E);
    cudaEventRecord(evA, 0);

    // Side chain: scan + permute (need deg_in) overlap gemm (needs deg_out).
    cudaStreamWaitEvent(s2, evA, 0);
    scan_kernel<<<N_CHUNKS, 256, 0, s2>>>();
    permute_kernel<<<(E / 4 + 255) / 256, 256, 0, s2>>>(src, dst, E);
    cudaEventRecord(evB, s2);

    gemm_scale_kernel<<<(N_NODES + 127) / 128, 128>>>(x, W);

    cudaStreamWaitEvent(0, evB, 0);
    aggregate_kernel<<<(N_NODES * 32 + 255) / 256, 256>>>(b, out);
}